// round 15
// baseline (speedup 1.0000x reference)
#include <cuda_runtime.h>
#include <cstdint>

// SelfAttentionHead via tf32 mma.sync (sm_100 toolchain: no tcgen05).
// R15: GEMM warp tile 32x64 -> 64x64 (block 256x128): 1.0 LDS/MMA (was 1.5).
// Attention = R11 (measured best, untouched).
// B=16, T=2048, DM=1024, DK=128, fp32 in/out.

#define NB 16
#define T 2048
#define DM 1024
#define DK 128
#define BT (NB * T)

#define QFP 132
#define KFP 66
#define NQT (T / 128)          // 16 q-tiles

__device__ float g_qkv[3][(size_t)BT * DK];

__device__ __forceinline__ unsigned f2tf(float f) {
    unsigned u; asm("cvt.rna.tf32.f32 %0, %1;" : "=r"(u) : "f"(f)); return u;
}
__device__ __forceinline__ float f2tff(float f) { return __uint_as_float(f2tf(f)); }
__device__ __forceinline__ float fexp2(float x) {
    float r; asm("ex2.approx.ftz.f32 %0, %1;" : "=f"(r) : "f"(x)); return r;
}

#define MMA_TF32(d, a0, a1, a2, a3, b0, b1)                                  \
    asm volatile("mma.sync.aligned.m16n8k8.row.col.f32.tf32.tf32.f32 "       \
                 "{%0,%1,%2,%3}, {%4,%5,%6,%7}, {%8,%9}, {%0,%1,%2,%3};"     \
                 : "+f"(d[0]), "+f"(d[1]), "+f"(d[2]), "+f"(d[3])            \
                 : "r"(a0), "r"(a1), "r"(a2), "r"(a3), "r"(b0), "r"(b1))

// ===========================================================================
// QKV GEMM: out[sel] = x @ W_sel.  M=32768, K=1024, N=128.
// R15: block tile 256x128, 8 warps (4m x 2n), warp tile 64x64, KC=16,
// double-buffered dynamic smem. Per k8-slice/warp: 32 MMAs from 32 LDS.32.
// ===========================================================================
#define KC 16
#define GAP 20
#define GBP 136
#define NIT (DM / KC)

struct __align__(16) GemmSmem {
    float As[2][256 * GAP];    // 40 KB
    float Bs[2][KC * GBP];     // 17 KB
};
extern __shared__ char gemm_raw[];

__global__ void __launch_bounds__(256) qkv_gemm_kernel(
    const float* __restrict__ x, const float* __restrict__ Wq,
    const float* __restrict__ Wk, const float* __restrict__ Wv)
{
    GemmSmem& sm = *reinterpret_cast<GemmSmem*>(gemm_raw);

    const int sel = blockIdx.x;
    const float* W = (sel == 0) ? Wq : (sel == 1 ? Wk : Wv);
    float* outp = g_qkv[sel];
    const int m0 = blockIdx.y * 256;

    const int t = threadIdx.x;
    const int lane = t & 31, wid = t >> 5;
    const int wm = wid >> 1, wn = wid & 1;      // 4m x 2n
    const int lq = lane >> 2, lr = lane & 3;

    const float* xp = x + (size_t)m0 * DM;

    // A: 256x16 floats -> 4 float4/thread: row f>>2, col4 (f&3)*4
    // B: 16x128 floats -> 2 float4/thread: row f>>5, col4 (f&31)*4
    float4 ra[4], rb[2];

    float c[4][8][4];
    #pragma unroll
    for (int mt = 0; mt < 4; mt++)
        #pragma unroll
        for (int nt = 0; nt < 8; nt++)
            #pragma unroll
            for (int k = 0; k < 4; k++) c[mt][nt][k] = 0.0f;

    // ---- prologue: tile 0 -> buf 0, LDG tile 1 into regs ----
    #pragma unroll
    for (int i = 0; i < 4; i++) {
        int f = t + 256 * i;
        ra[i] = *(const float4*)(xp + (size_t)(f >> 2) * DM + (f & 3) * 4);
    }
    #pragma unroll
    for (int i = 0; i < 2; i++) {
        int f = t + 256 * i;
        rb[i] = *(const float4*)(W + (size_t)(f >> 5) * DK + (f & 31) * 4);
    }
    #pragma unroll
    for (int i = 0; i < 4; i++) {
        int f = t + 256 * i;
        float4 a = ra[i];
        float* ap = &sm.As[0][(f >> 2) * GAP + (f & 3) * 4];
        ap[0] = f2tff(a.x); ap[1] = f2tff(a.y);
        ap[2] = f2tff(a.z); ap[3] = f2tff(a.w);
    }
    #pragma unroll
    for (int i = 0; i < 2; i++) {
        int f = t + 256 * i;
        float4 bv = rb[i];
        float* bp = &sm.Bs[0][(f >> 5) * GBP + (f & 31) * 4];
        bp[0] = f2tff(bv.x); bp[1] = f2tff(bv.y);
        bp[2] = f2tff(bv.z); bp[3] = f2tff(bv.w);
    }
    #pragma unroll
    for (int i = 0; i < 4; i++) {
        int f = t + 256 * i;
        ra[i] = *(const float4*)(xp + (size_t)(f >> 2) * DM + KC + (f & 3) * 4);
    }
    #pragma unroll
    for (int i = 0; i < 2; i++) {
        int f = t + 256 * i;
        rb[i] = *(const float4*)(W + (size_t)(KC + (f >> 5)) * DK + (f & 31) * 4);
    }
    __syncthreads();

    for (int kt = 0; kt < NIT; kt++) {
        const int p = kt & 1;

        // ---- compute on buffer p (next tile's LDG already in flight) ----
        #pragma unroll
        for (int kk = 0; kk < KC; kk += 8) {
            unsigned a[4][4];
            #pragma unroll
            for (int mt = 0; mt < 4; mt++) {
                int r = wm * 64 + mt * 16 + lq;
                a[mt][0] = __float_as_uint(sm.As[p][r * GAP + kk + lr]);
                a[mt][1] = __float_as_uint(sm.As[p][(r + 8) * GAP + kk + lr]);
                a[mt][2] = __float_as_uint(sm.As[p][r * GAP + kk + 4 + lr]);
                a[mt][3] = __float_as_uint(sm.As[p][(r + 8) * GAP + kk + 4 + lr]);
            }
            #pragma unroll
            for (int nt = 0; nt < 8; nt++) {
                int col = wn * 64 + nt * 8 + lq;
                unsigned b0 = __float_as_uint(sm.Bs[p][(kk + lr) * GBP + col]);
                unsigned b1 = __float_as_uint(sm.Bs[p][(kk + 4 + lr) * GBP + col]);
                #pragma unroll
                for (int mt = 0; mt < 4; mt++)
                    MMA_TF32(c[mt][nt], a[mt][0], a[mt][1], a[mt][2], a[mt][3], b0, b1);
            }
        }

        // ---- stage tile kt+1 into buf p^1, issue LDG for tile kt+2 ----
        if (kt + 1 < NIT) {
            #pragma unroll
            for (int i = 0; i < 4; i++) {
                int f = t + 256 * i;
                float4 a = ra[i];
                float* ap = &sm.As[p ^ 1][(f >> 2) * GAP + (f & 3) * 4];
                ap[0] = f2tff(a.x); ap[1] = f2tff(a.y);
                ap[2] = f2tff(a.z); ap[3] = f2tff(a.w);
            }
            #pragma unroll
            for (int i = 0; i < 2; i++) {
                int f = t + 256 * i;
                float4 bv = rb[i];
                float* bp = &sm.Bs[p ^ 1][(f >> 5) * GBP + (f & 31) * 4];
                bp[0] = f2tff(bv.x); bp[1] = f2tff(bv.y);
                bp[2] = f2tff(bv.z); bp[3] = f2tff(bv.w);
            }
            if (kt + 2 < NIT) {
                const int k0 = (kt + 2) * KC;
                #pragma unroll
                for (int i = 0; i < 4; i++) {
                    int f = t + 256 * i;
                    ra[i] = *(const float4*)(xp + (size_t)(f >> 2) * DM + k0 + (f & 3) * 4);
                }
                #pragma unroll
                for (int i = 0; i < 2; i++) {
                    int f = t + 256 * i;
                    rb[i] = *(const float4*)(W + (size_t)(k0 + (f >> 5)) * DK + (f & 31) * 4);
                }
            }
            __syncthreads();
        }
    }

    #pragma unroll
    for (int mt = 0; mt < 4; mt++) {
        int row = m0 + wm * 64 + mt * 16 + lq;
        #pragma unroll
        for (int nt = 0; nt < 8; nt++) {
            int col = wn * 64 + nt * 8 + 2 * lr;
            *(float2*)(outp + (size_t)row * DK + col) =
                make_float2(c[mt][nt][0], c[mt][nt][1]);
            *(float2*)(outp + (size_t)(row + 8) * DK + col) =
                make_float2(c[mt][nt][2], c[mt][nt][3]);
        }
    }
}

// ===========================================================================
// Flash attention (R11, measured best): BM=128 x BN=64, 8 full-row warps,
// register softmax, double-buffered K/V, 1 sync/iter, pi-permuted V.
// grid (8, 16); CTA bx handles q-tiles {15-bx, bx} -> one balanced wave.
// ===========================================================================
struct __align__(16) AttnSmem {
    float Qf[128 * QFP];
    float Kf[2][128 * KFP];
    float Vf[2][128 * KFP];
};
extern __shared__ char attn_raw[];

__device__ __forceinline__ void sts_k(float* Kb, float4 v, int f) {
    int r = f >> 5, c4 = f & 31;
    int ng = r >> 3, lqq = r & 7, kkc = c4 >> 1, s = c4 & 1;
    float* kp = &Kb[(ng * 16 + kkc) * KFP + s];
    kp[(lqq * 4 + 0) * 2] = f2tff(v.x);
    kp[(lqq * 4 + 1) * 2] = f2tff(v.y);
    kp[(lqq * 4 + 2) * 2] = f2tff(v.z);
    kp[(lqq * 4 + 3) * 2] = f2tff(v.w);
}
// pi-permuted V store (pi(j)=2j / 2(j-4)+1): row g -> (lrr=g>>1, s=g&1)
__device__ __forceinline__ void sts_v(float* Vb, float4 v, int f) {
    int r = f >> 5, c4 = f & 31;
    int kkc = r >> 3, g = r & 7;
    int lrr = g >> 1, s = g & 1;
    int ng = c4 >> 1, lq0 = 4 * (c4 & 1);
    float* vp = &Vb[(kkc * 16 + ng) * KFP + lrr * 2 + s];
    vp[(lq0 + 0) * 8] = f2tff(v.x);
    vp[(lq0 + 1) * 8] = f2tff(v.y);
    vp[(lq0 + 2) * 8] = f2tff(v.z);
    vp[(lq0 + 3) * 8] = f2tff(v.w);
}

__global__ void __launch_bounds__(256, 1) attn_kernel(float* __restrict__ out)
{
    AttnSmem& sm = *reinterpret_cast<AttnSmem*>(attn_raw);
    const int t = threadIdx.x;
    const int lane = t & 31, wm = t >> 5;
    const int lq = lane >> 2, lr = lane & 3;
    const int b = blockIdx.y;

    const float* Q = g_qkv[0] + (size_t)b * T * DK;
    const float* K = g_qkv[1] + (size_t)b * T * DK;
    const float* V = g_qkv[2] + (size_t)b * T * DK;

    const float C = 0.12751744154255254f;   // (1/sqrt(128)) * log2(e)
    const int r1 = 16 * wm + lq;

    #pragma unroll 1
    for (int hh = 0; hh < 2; hh++) {
        const int qbi = hh ? (int)blockIdx.x : (NQT - 1) - (int)blockIdx.x;
        const int q0 = qbi * 128;

        if (hh) __syncthreads();   // half-0 tail done reading Qf / buffers

        // ---- Q -> fragment-major smem ----
        #pragma unroll
        for (int i = 0; i < 16; i++) {
            int f = t + 256 * i;
            int r = f >> 5, c4 = f & 31;
            float4 qv = *(const float4*)(Q + (size_t)(q0 + r) * DK + 4 * c4);
            int rg = r >> 4, lqq = r & 7, half = (r >> 3) & 1;
            int kkc = c4 >> 1, khalf = c4 & 1;
            float* qp = &sm.Qf[(rg * 16 + kkc) * QFP + half + 2 * khalf];
            qp[(lqq * 4 + 0) * 4] = f2tff(qv.x);
            qp[(lqq * 4 + 1) * 4] = f2tff(qv.y);
            qp[(lqq * 4 + 2) * 4] = f2tff(qv.z);
            qp[(lqq * 4 + 3) * 4] = f2tff(qv.w);
        }

        float4 kreg[8], vreg[8];
        #pragma unroll
        for (int i = 0; i < 8; i++) {
            int f = t + 256 * i;
            int r = f >> 5, c4 = f & 31;
            kreg[i] = *(const float4*)(K + (size_t)r * DK + 4 * c4);
            vreg[i] = *(const float4*)(V + (size_t)r * DK + 4 * c4);
        }
        #pragma unroll
        for (int i = 0; i < 8; i++) {
            sts_k(sm.Kf[0], kreg[i], t + 256 * i);
            sts_v(sm.Vf[0], vreg[i], t + 256 * i);
        }
        __syncthreads();

        float m1 = -1e30f, m2 = -1e30f, l1 = 0.0f, l2 = 0.0f;

        float o[16][4];
        #pragma unroll
        for (int ng = 0; ng < 16; ng++)
            #pragma unroll
            for (int k = 0; k < 4; k++) o[ng][k] = 0.0f;

        const float* qbase = &sm.Qf[(wm * 16) * QFP + lane * 4];
        const int qbend = 2 * qbi + 1;
        int p = 0;

        for (int kb = 0; kb <= qbend; kb++) {
            const int k0 = kb * 64;

            if (kb < qbend) {
                #pragma unroll
                for (int i = 0; i < 8; i++) {
                    int f = t + 256 * i;
                    kreg[i] = *(const float4*)(K + (size_t)(k0 + 64 + (f >> 5)) * DK + 4 * (f & 31));
                }
            }

            float sc[8][4];
            #pragma unroll
            for (int nt = 0; nt < 8; nt++)
                #pragma unroll
                for (int k = 0; k < 4; k++) sc[nt][k] = 0.0f;

            const float* kfb = &sm.Kf[p][lane * 2];
            #pragma unroll
            for (int kkc = 0; kkc < 16; kkc++) {
                float4 A = *(const float4*)(qbase + kkc * QFP);
                unsigned a0 = __float_as_uint(A.x), a1 = __float_as_uint(A.y);
                unsigned a2 = __float_as_uint(A.z), a3 = __float_as_uint(A.w);
                #pragma unroll
                for (int nt = 0; nt < 8; nt++) {
                    float2 Bv = *(const float2*)(kfb + (nt * 16 + kkc) * KFP);
                    MMA_TF32(sc[nt], a0, a1, a2, a3,
                             __float_as_uint(Bv.x), __float_as_uint(Bv.y));
                }
            }

            if (kb < qbend) {
                #pragma unroll
                for (int i = 0; i < 8; i++) {
                    int f = t + 256 * i;
                    vreg[i] = *(const float4*)(V + (size_t)(k0 + 64 + (f >> 5)) * DK + 4 * (f & 31));
                }
            }

            // causal mask on raw scores (scale folded into exp2 constant)
            if (kb >= 2 * qbi) {
                int gr1 = q0 + r1;
                #pragma unroll
                for (int nt = 0; nt < 8; nt++) {
                    int gc = k0 + nt * 8 + 2 * lr;
                    if (gc     > gr1)     sc[nt][0] = -1e30f;
                    if (gc + 1 > gr1)     sc[nt][1] = -1e30f;
                    if (gc     > gr1 + 8) sc[nt][2] = -1e30f;
                    if (gc + 1 > gr1 + 8) sc[nt][3] = -1e30f;
                }
            }

            float mx1 = -1e30f, mx2 = -1e30f;
            #pragma unroll
            for (int nt = 0; nt < 8; nt++) {
                mx1 = fmaxf(mx1, fmaxf(sc[nt][0], sc[nt][1]));
                mx2 = fmaxf(mx2, fmaxf(sc[nt][2], sc[nt][3]));
            }
            mx1 = fmaxf(mx1, __shfl_xor_sync(0xffffffffu, mx1, 1));
            mx1 = fmaxf(mx1, __shfl_xor_sync(0xffffffffu, mx1, 2));
            mx2 = fmaxf(mx2, __shfl_xor_sync(0xffffffffu, mx2, 1));
            mx2 = fmaxf(mx2, __shfl_xor_sync(0xffffffffu, mx2, 2));

            float mn1 = fmaxf(m1, mx1), mn2 = fmaxf(m2, mx2);
            float pc1 = fexp2((m1 - mn1) * C), pc2 = fexp2((m2 - mn2) * C);
            m1 = mn1; m2 = mn2;

            float s1 = 0.0f, s2 = 0.0f;
            #pragma unroll
            for (int nt = 0; nt < 8; nt++) {
                sc[nt][0] = fexp2((sc[nt][0] - m1) * C);
                sc[nt][1] = fexp2((sc[nt][1] - m1) * C);
                sc[nt][2] = fexp2((sc[nt][2] - m2) * C);
                sc[nt][3] = fexp2((sc[nt][3] - m2) * C);
                s1 += sc[nt][0] + sc[nt][1];
                s2 += sc[nt][2] + sc[nt][3];
            }
            s1 += __shfl_xor_sync(0xffffffffu, s1, 1);
            s1 += __shfl_xor_sync(0xffffffffu, s1, 2);
            s2 += __shfl_xor_sync(0xffffffffu, s2, 1);
            s2 += __shfl_xor_sync(0xffffffffu, s2, 2);
            l1 = l1 * pc1 + s1;
            l2 = l2 * pc2 + s2;

            #pragma unroll
            for (int ng = 0; ng < 16; ng++) {
                o[ng][0] *= pc1; o[ng][1] *= pc1;
                o[ng][2] *= pc2; o[ng][3] *= pc2;
            }

            // ---- PV: accumulators feed A fragments directly ----
            const float* vfb = &sm.Vf[p][lane * 2];
            #pragma unroll
            for (int c = 0; c < 8; c++) {
                unsigned a0 = f2tf(sc[c][0]);
                unsigned a1 = f2tf(sc[c][2]);
                unsigned a2 = f2tf(sc[c][1]);
                unsigned a3 = f2tf(sc[c][3]);
                const float* vb = vfb + (c * 16) * KFP;
                #pragma unroll
                for (int ng = 0; ng < 16; ng++) {
                    float2 Bv = *(const float2*)(vb + ng * KFP);
                    MMA_TF32(o[ng], a0, a1, a2, a3,
                             __float_as_uint(Bv.x), __float_as_uint(Bv.y));
                }
            }

            if (kb < qbend) {
                #pragma unroll
                for (int i = 0; i < 8; i++) {
                    sts_k(sm.Kf[p ^ 1], kreg[i], t + 256 * i);
                    sts_v(sm.Vf[p ^ 1], vreg[i], t + 256 * i);
                }
                __syncthreads();
            }
            p ^= 1;
        }

        // ---- epilogue: normalize and store this q-tile ----
        {
            float inv1 = 1.0f / l1, inv2 = 1.0f / l2;
            float* op = out + ((size_t)b * T + q0) * DK;
            #pragma unroll
            for (int ng = 0; ng < 16; ng++) {
                int cb = ng * 8 + 2 * lr;
                *(float2*)(op + (size_t)r1 * DK + cb) =
                    make_float2(o[ng][0] * inv1, o[ng][1] * inv1);
                *(float2*)(op + (size_t)(r1 + 8) * DK + cb) =
                    make_float2(o[ng][2] * inv2, o[ng][3] * inv2);
            }
        }
    }
}

// ===========================================================================
extern "C" void kernel_launch(void* const* d_in, const int* in_sizes, int n_in,
                              void* d_out, int out_size)
{
    const float* x  = (const float*)d_in[0];
    const float* Wq = (const float*)d_in[1];
    const float* Wk = (const float*)d_in[2];
    const float* Wv = (const float*)d_in[3];
    float* out = (float*)d_out;

    int gsmem = (int)sizeof(GemmSmem);
    cudaFuncSetAttribute(qkv_gemm_kernel, cudaFuncAttributeMaxDynamicSharedMemorySize, gsmem);
    dim3 g1(3, BT / 256);
    qkv_gemm_kernel<<<g1, 256, (size_t)gsmem>>>(x, Wq, Wk, Wv);

    int asmem = (int)sizeof(AttnSmem);
    cudaFuncSetAttribute(attn_kernel, cudaFuncAttributeMaxDynamicSharedMemorySize, asmem);
    dim3 g2(NQT / 2, NB);
    attn_kernel<<<g2, 256, (size_t)asmem>>>(out);
}

// round 16
// speedup vs baseline: 1.0617x; 1.0617x over previous
#include <cuda_runtime.h>
#include <cstdint>

// SelfAttentionHead via tf32 mma.sync (sm_100 toolchain: no tcgen05).
// R16: GEMM rebuilt: 64x64 warp tile + cp.async 3-stage pipeline (no register
// staging, no STS pass; tf32 cvt in-register post-LDS). 128-thr CTAs, 2/SM.
// Attention = R11 (measured best, untouched).
// B=16, T=2048, DM=1024, DK=128, fp32 in/out.

#define NB 16
#define T 2048
#define DM 1024
#define DK 128
#define BT (NB * T)

#define QFP 132
#define KFP 66
#define NQT (T / 128)          // 16 q-tiles

__device__ float g_qkv[3][(size_t)BT * DK];

__device__ __forceinline__ unsigned f2tf(float f) {
    unsigned u; asm("cvt.rna.tf32.f32 %0, %1;" : "=r"(u) : "f"(f)); return u;
}
__device__ __forceinline__ float f2tff(float f) { return __uint_as_float(f2tf(f)); }
__device__ __forceinline__ float fexp2(float x) {
    float r; asm("ex2.approx.ftz.f32 %0, %1;" : "=f"(r) : "f"(x)); return r;
}
__device__ __forceinline__ uint32_t smem_u32(const void* p) {
    uint32_t a;
    asm("{ .reg .u64 t; cvta.to.shared.u64 t, %1; cvt.u32.u64 %0, t; }"
        : "=r"(a) : "l"(p));
    return a;
}

#define MMA_TF32(d, a0, a1, a2, a3, b0, b1)                                  \
    asm volatile("mma.sync.aligned.m16n8k8.row.col.f32.tf32.tf32.f32 "       \
                 "{%0,%1,%2,%3}, {%4,%5,%6,%7}, {%8,%9}, {%0,%1,%2,%3};"     \
                 : "+f"(d[0]), "+f"(d[1]), "+f"(d[2]), "+f"(d[3])            \
                 : "r"(a0), "r"(a1), "r"(a2), "r"(a3), "r"(b0), "r"(b1))

#define CP16(dst, src) \
    asm volatile("cp.async.ca.shared.global [%0], [%1], 16;" \
                 :: "r"(dst), "l"(src) : "memory")
#define CP_COMMIT() asm volatile("cp.async.commit_group;" ::: "memory")
#define CP_WAIT1()  asm volatile("cp.async.wait_group 1;" ::: "memory")

// ===========================================================================
// QKV GEMM: out[sel] = x @ W_sel.  M=32768, K=1024, N=128.
// grid (3, 256), 128 threads = 4 warps (2m x 2n), warp tile 64x64, KC=16.
// 3-stage cp.async pipeline; raw fp32 in smem; cvt.rna post-LDS.
// Pitches: GAP=20 (80 B rows, 16B-aligned chunks), GBP=136 (544 B rows).
// ===========================================================================
#define KC 16
#define GAP 20
#define GBP 136
#define NIT (DM / KC)
#define A_ELE (128 * GAP)          // 2560 floats
#define B_ELE (KC * GBP)           // 2176 floats
#define STG (A_ELE + B_ELE)        // 4736 floats = 18944 B (16B-multiple)
#define NSTG 3

extern __shared__ char gemm_raw[];

__global__ void __launch_bounds__(128) qkv_gemm_kernel(
    const float* __restrict__ x, const float* __restrict__ Wq,
    const float* __restrict__ Wk, const float* __restrict__ Wv)
{
    float* sb = reinterpret_cast<float*>(gemm_raw);
    const uint32_t sb_u32 = smem_u32(sb);

    const int sel = blockIdx.x;
    const float* W = (sel == 0) ? Wq : (sel == 1 ? Wk : Wv);
    float* outp = g_qkv[sel];
    const int m0 = blockIdx.y * 128;

    const int t = threadIdx.x;
    const int lane = t & 31, wid = t >> 5;
    const int wm = wid >> 1, wn = wid & 1;     // 2m x 2n
    const int lq = lane >> 2, lr = lane & 3;

    const float* xp = x + (size_t)m0 * DM;

    // per-thread copy mapping (8 x 16B chunks per tile):
    //   A: f = t + 128*i (i<4): row f>>2 (0..127), chunk f&3 (4 x 16B = 64B row)
    //   B: row f>>5 (0..15), chunk f&31 (32 x 16B... 128 floats = 512B row)
    float c[4][8][4];
    #pragma unroll
    for (int mt = 0; mt < 4; mt++)
        #pragma unroll
        for (int nt = 0; nt < 8; nt++)
            #pragma unroll
            for (int k = 0; k < 4; k++) c[mt][nt][k] = 0.0f;

    // ---- issue one tile's copies into stage s ----
    auto issue = [&](int kt, int s) {
        const uint32_t abase = sb_u32 + (uint32_t)(s * STG) * 4u;
        const uint32_t bbase = abase + (uint32_t)A_ELE * 4u;
        #pragma unroll
        for (int i = 0; i < 4; i++) {
            int f = t + 128 * i;
            int ar = f >> 2, ac = f & 3;
            CP16(abase + (uint32_t)(ar * GAP + ac * 4) * 4u,
                 xp + (size_t)ar * DM + kt * KC + ac * 4);
            int br = f >> 5, bc = f & 31;
            CP16(bbase + (uint32_t)(br * GBP + bc * 4) * 4u,
                 W + (size_t)(kt * KC + br) * DK + bc * 4);
        }
    };

    // ---- prologue: tiles 0 and 1 ----
    issue(0, 0); CP_COMMIT();
    issue(1, 1); CP_COMMIT();

    for (int kt = 0; kt < NIT; kt++) {
        CP_WAIT1();             // group for tile kt has landed (this thread)
        __syncthreads();        // visible to all; prev compute done by all

        if (kt + 2 < NIT) issue(kt + 2, (kt + 2) % NSTG);
        CP_COMMIT();            // always commit (possibly empty group)

        const float* As = sb + (kt % NSTG) * STG;
        const float* Bs = As + A_ELE;

        #pragma unroll
        for (int kk = 0; kk < KC; kk += 8) {
            unsigned a[4][4];
            #pragma unroll
            for (int mt = 0; mt < 4; mt++) {
                int r = wm * 64 + mt * 16 + lq;
                a[mt][0] = f2tf(As[r * GAP + kk + lr]);
                a[mt][1] = f2tf(As[(r + 8) * GAP + kk + lr]);
                a[mt][2] = f2tf(As[r * GAP + kk + 4 + lr]);
                a[mt][3] = f2tf(As[(r + 8) * GAP + kk + 4 + lr]);
            }
            #pragma unroll
            for (int nt = 0; nt < 8; nt++) {
                int col = wn * 64 + nt * 8 + lq;
                unsigned b0 = f2tf(Bs[(kk + lr) * GBP + col]);
                unsigned b1 = f2tf(Bs[(kk + 4 + lr) * GBP + col]);
                #pragma unroll
                for (int mt = 0; mt < 4; mt++)
                    MMA_TF32(c[mt][nt], a[mt][0], a[mt][1], a[mt][2], a[mt][3], b0, b1);
            }
        }
    }

    #pragma unroll
    for (int mt = 0; mt < 4; mt++) {
        int row = m0 + wm * 64 + mt * 16 + lq;
        #pragma unroll
        for (int nt = 0; nt < 8; nt++) {
            int col = wn * 64 + nt * 8 + 2 * lr;
            *(float2*)(outp + (size_t)row * DK + col) =
                make_float2(c[mt][nt][0], c[mt][nt][1]);
            *(float2*)(outp + (size_t)(row + 8) * DK + col) =
                make_float2(c[mt][nt][2], c[mt][nt][3]);
        }
    }
}

// ===========================================================================
// Flash attention (R11, measured best): BM=128 x BN=64, 8 full-row warps,
// register softmax, double-buffered K/V, 1 sync/iter, pi-permuted V.
// grid (8, 16); CTA bx handles q-tiles {15-bx, bx} -> one balanced wave.
// ===========================================================================
struct __align__(16) AttnSmem {
    float Qf[128 * QFP];
    float Kf[2][128 * KFP];
    float Vf[2][128 * KFP];
};
extern __shared__ char attn_raw[];

__device__ __forceinline__ void sts_k(float* Kb, float4 v, int f) {
    int r = f >> 5, c4 = f & 31;
    int ng = r >> 3, lqq = r & 7, kkc = c4 >> 1, s = c4 & 1;
    float* kp = &Kb[(ng * 16 + kkc) * KFP + s];
    kp[(lqq * 4 + 0) * 2] = f2tff(v.x);
    kp[(lqq * 4 + 1) * 2] = f2tff(v.y);
    kp[(lqq * 4 + 2) * 2] = f2tff(v.z);
    kp[(lqq * 4 + 3) * 2] = f2tff(v.w);
}
// pi-permuted V store (pi(j)=2j / 2(j-4)+1): row g -> (lrr=g>>1, s=g&1)
__device__ __forceinline__ void sts_v(float* Vb, float4 v, int f) {
    int r = f >> 5, c4 = f & 31;
    int kkc = r >> 3, g = r & 7;
    int lrr = g >> 1, s = g & 1;
    int ng = c4 >> 1, lq0 = 4 * (c4 & 1);
    float* vp = &Vb[(kkc * 16 + ng) * KFP + lrr * 2 + s];
    vp[(lq0 + 0) * 8] = f2tff(v.x);
    vp[(lq0 + 1) * 8] = f2tff(v.y);
    vp[(lq0 + 2) * 8] = f2tff(v.z);
    vp[(lq0 + 3) * 8] = f2tff(v.w);
}

__global__ void __launch_bounds__(256, 1) attn_kernel(float* __restrict__ out)
{
    AttnSmem& sm = *reinterpret_cast<AttnSmem*>(attn_raw);
    const int t = threadIdx.x;
    const int lane = t & 31, wm = t >> 5;
    const int lq = lane >> 2, lr = lane & 3;
    const int b = blockIdx.y;

    const float* Q = g_qkv[0] + (size_t)b * T * DK;
    const float* K = g_qkv[1] + (size_t)b * T * DK;
    const float* V = g_qkv[2] + (size_t)b * T * DK;

    const float C = 0.12751744154255254f;   // (1/sqrt(128)) * log2(e)
    const int r1 = 16 * wm + lq;

    #pragma unroll 1
    for (int hh = 0; hh < 2; hh++) {
        const int qbi = hh ? (int)blockIdx.x : (NQT - 1) - (int)blockIdx.x;
        const int q0 = qbi * 128;

        if (hh) __syncthreads();   // half-0 tail done reading Qf / buffers

        // ---- Q -> fragment-major smem ----
        #pragma unroll
        for (int i = 0; i < 16; i++) {
            int f = t + 256 * i;
            int r = f >> 5, c4 = f & 31;
            float4 qv = *(const float4*)(Q + (size_t)(q0 + r) * DK + 4 * c4);
            int rg = r >> 4, lqq = r & 7, half = (r >> 3) & 1;
            int kkc = c4 >> 1, khalf = c4 & 1;
            float* qp = &sm.Qf[(rg * 16 + kkc) * QFP + half + 2 * khalf];
            qp[(lqq * 4 + 0) * 4] = f2tff(qv.x);
            qp[(lqq * 4 + 1) * 4] = f2tff(qv.y);
            qp[(lqq * 4 + 2) * 4] = f2tff(qv.z);
            qp[(lqq * 4 + 3) * 4] = f2tff(qv.w);
        }

        float4 kreg[8], vreg[8];
        #pragma unroll
        for (int i = 0; i < 8; i++) {
            int f = t + 256 * i;
            int r = f >> 5, c4 = f & 31;
            kreg[i] = *(const float4*)(K + (size_t)r * DK + 4 * c4);
            vreg[i] = *(const float4*)(V + (size_t)r * DK + 4 * c4);
        }
        #pragma unroll
        for (int i = 0; i < 8; i++) {
            sts_k(sm.Kf[0], kreg[i], t + 256 * i);
            sts_v(sm.Vf[0], vreg[i], t + 256 * i);
        }
        __syncthreads();

        float m1 = -1e30f, m2 = -1e30f, l1 = 0.0f, l2 = 0.0f;

        float o[16][4];
        #pragma unroll
        for (int ng = 0; ng < 16; ng++)
            #pragma unroll
            for (int k = 0; k < 4; k++) o[ng][k] = 0.0f;

        const float* qbase = &sm.Qf[(wm * 16) * QFP + lane * 4];
        const int qbend = 2 * qbi + 1;
        int p = 0;

        for (int kb = 0; kb <= qbend; kb++) {
            const int k0 = kb * 64;

            if (kb < qbend) {
                #pragma unroll
                for (int i = 0; i < 8; i++) {
                    int f = t + 256 * i;
                    kreg[i] = *(const float4*)(K + (size_t)(k0 + 64 + (f >> 5)) * DK + 4 * (f & 31));
                }
            }

            float sc[8][4];
            #pragma unroll
            for (int nt = 0; nt < 8; nt++)
                #pragma unroll
                for (int k = 0; k < 4; k++) sc[nt][k] = 0.0f;

            const float* kfb = &sm.Kf[p][lane * 2];
            #pragma unroll
            for (int kkc = 0; kkc < 16; kkc++) {
                float4 A = *(const float4*)(qbase + kkc * QFP);
                unsigned a0 = __float_as_uint(A.x), a1 = __float_as_uint(A.y);
                unsigned a2 = __float_as_uint(A.z), a3 = __float_as_uint(A.w);
                #pragma unroll
                for (int nt = 0; nt < 8; nt++) {
                    float2 Bv = *(const float2*)(kfb + (nt * 16 + kkc) * KFP);
                    MMA_TF32(sc[nt], a0, a1, a2, a3,
                             __float_as_uint(Bv.x), __float_as_uint(Bv.y));
                }
            }

            if (kb < qbend) {
                #pragma unroll
                for (int i = 0; i < 8; i++) {
                    int f = t + 256 * i;
                    vreg[i] = *(const float4*)(V + (size_t)(k0 + 64 + (f >> 5)) * DK + 4 * (f & 31));
                }
            }

            // causal mask on raw scores (scale folded into exp2 constant)
            if (kb >= 2 * qbi) {
                int gr1 = q0 + r1;
                #pragma unroll
                for (int nt = 0; nt < 8; nt++) {
                    int gc = k0 + nt * 8 + 2 * lr;
                    if (gc     > gr1)     sc[nt][0] = -1e30f;
                    if (gc + 1 > gr1)     sc[nt][1] = -1e30f;
                    if (gc     > gr1 + 8) sc[nt][2] = -1e30f;
                    if (gc + 1 > gr1 + 8) sc[nt][3] = -1e30f;
                }
            }

            float mx1 = -1e30f, mx2 = -1e30f;
            #pragma unroll
            for (int nt = 0; nt < 8; nt++) {
                mx1 = fmaxf(mx1, fmaxf(sc[nt][0], sc[nt][1]));
                mx2 = fmaxf(mx2, fmaxf(sc[nt][2], sc[nt][3]));
            }
            mx1 = fmaxf(mx1, __shfl_xor_sync(0xffffffffu, mx1, 1));
            mx1 = fmaxf(mx1, __shfl_xor_sync(0xffffffffu, mx1, 2));
            mx2 = fmaxf(mx2, __shfl_xor_sync(0xffffffffu, mx2, 1));
            mx2 = fmaxf(mx2, __shfl_xor_sync(0xffffffffu, mx2, 2));

            float mn1 = fmaxf(m1, mx1), mn2 = fmaxf(m2, mx2);
            float pc1 = fexp2((m1 - mn1) * C), pc2 = fexp2((m2 - mn2) * C);
            m1 = mn1; m2 = mn2;

            float s1 = 0.0f, s2 = 0.0f;
            #pragma unroll
            for (int nt = 0; nt < 8; nt++) {
                sc[nt][0] = fexp2((sc[nt][0] - m1) * C);
                sc[nt][1] = fexp2((sc[nt][1] - m1) * C);
                sc[nt][2] = fexp2((sc[nt][2] - m2) * C);
                sc[nt][3] = fexp2((sc[nt][3] - m2) * C);
                s1 += sc[nt][0] + sc[nt][1];
                s2 += sc[nt][2] + sc[nt][3];
            }
            s1 += __shfl_xor_sync(0xffffffffu, s1, 1);
            s1 += __shfl_xor_sync(0xffffffffu, s1, 2);
            s2 += __shfl_xor_sync(0xffffffffu, s2, 1);
            s2 += __shfl_xor_sync(0xffffffffu, s2, 2);
            l1 = l1 * pc1 + s1;
            l2 = l2 * pc2 + s2;

            #pragma unroll
            for (int ng = 0; ng < 16; ng++) {
                o[ng][0] *= pc1; o[ng][1] *= pc1;
                o[ng][2] *= pc2; o[ng][3] *= pc2;
            }

            // ---- PV: accumulators feed A fragments directly ----
            const float* vfb = &sm.Vf[p][lane * 2];
            #pragma unroll
            for (int c = 0; c < 8; c++) {
                unsigned a0 = f2tf(sc[c][0]);
                unsigned a1 = f2tf(sc[c][2]);
                unsigned a2 = f2tf(sc[c][1]);
                unsigned a3 = f2tf(sc[c][3]);
                const float* vb = vfb + (c * 16) * KFP;
                #pragma unroll
                for (int ng = 0; ng < 16; ng++) {
                    float2 Bv = *(const float2*)(vb + ng * KFP);
                    MMA_TF32(o[ng], a0, a1, a2, a3,
                             __float_as_uint(Bv.x), __float_as_uint(Bv.y));
                }
            }

            if (kb < qbend) {
                #pragma unroll
                for (int i = 0; i < 8; i++) {
                    sts_k(sm.Kf[p ^ 1], kreg[i], t + 256 * i);
                    sts_v(sm.Vf[p ^ 1], vreg[i], t + 256 * i);
                }
                __syncthreads();
            }
            p ^= 1;
        }

        // ---- epilogue: normalize and store this q-tile ----
        {
            float inv1 = 1.0f / l1, inv2 = 1.0f / l2;
            float* op = out + ((size_t)b * T + q0) * DK;
            #pragma unroll
            for (int ng = 0; ng < 16; ng++) {
                int cb = ng * 8 + 2 * lr;
                *(float2*)(op + (size_t)r1 * DK + cb) =
                    make_float2(o[ng][0] * inv1, o[ng][1] * inv1);
                *(float2*)(op + (size_t)(r1 + 8) * DK + cb) =
                    make_float2(o[ng][2] * inv2, o[ng][3] * inv2);
            }
        }
    }
}

// ===========================================================================
extern "C" void kernel_launch(void* const* d_in, const int* in_sizes, int n_in,
                              void* d_out, int out_size)
{
    const float* x  = (const float*)d_in[0];
    const float* Wq = (const float*)d_in[1];
    const float* Wk = (const float*)d_in[2];
    const float* Wv = (const float*)d_in[3];
    float* out = (float*)d_out;

    int gsmem = NSTG * STG * 4;
    cudaFuncSetAttribute(qkv_gemm_kernel, cudaFuncAttributeMaxDynamicSharedMemorySize, gsmem);
    dim3 g1(3, BT / 128);
    qkv_gemm_kernel<<<g1, 128, (size_t)gsmem>>>(x, Wq, Wk, Wv);

    int asmem = (int)sizeof(AttnSmem);
    cudaFuncSetAttribute(attn_kernel, cudaFuncAttributeMaxDynamicSharedMemorySize, asmem);
    dim3 g2(NQT / 2, NB);
    attn_kernel<<<g2, 256, (size_t)asmem>>>(out);
}

// round 17
// speedup vs baseline: 1.1057x; 1.0415x over previous
#include <cuda_runtime.h>
#include <cstdint>

// SelfAttentionHead via tf32 mma.sync (sm_100 toolchain: no tcgen05).
// R17: attention 9-group balanced schedule (max 16 units/CTA, 144 CTAs, one
// wave); GEMM = R12 (measured best ~200us). Attention body = R11 (proven).
// B=16, T=2048, DM=1024, DK=128, fp32 in/out.

#define NB 16
#define T 2048
#define DM 1024
#define DK 128
#define BT (NB * T)

#define QFP 132
#define KFP 66
#define NQT (T / 128)          // 16 q-tiles

__device__ float g_qkv[3][(size_t)BT * DK];

__device__ __forceinline__ unsigned f2tf(float f) {
    unsigned u; asm("cvt.rna.tf32.f32 %0, %1;" : "=r"(u) : "f"(f)); return u;
}
__device__ __forceinline__ float f2tff(float f) { return __uint_as_float(f2tf(f)); }
__device__ __forceinline__ float fexp2(float x) {
    float r; asm("ex2.approx.ftz.f32 %0, %1;" : "=f"(r) : "f"(x)); return r;
}

#define MMA_TF32(d, a0, a1, a2, a3, b0, b1)                                  \
    asm volatile("mma.sync.aligned.m16n8k8.row.col.f32.tf32.tf32.f32 "       \
                 "{%0,%1,%2,%3}, {%4,%5,%6,%7}, {%8,%9}, {%0,%1,%2,%3};"     \
                 : "+f"(d[0]), "+f"(d[1]), "+f"(d[2]), "+f"(d[3])            \
                 : "r"(a0), "r"(a1), "r"(a2), "r"(a3), "r"(b0), "r"(b1))

// ===========================================================================
// QKV GEMM (R12, measured best): out[sel] = x @ W_sel.
// grid (3, 256), 8 warps (4m x 2n), warp tile 32x64, KC=16, double-buffered.
// ===========================================================================
#define KC 16
#define GAP 20
#define GBP 136
#define NIT (DM / KC)

__global__ void __launch_bounds__(256, 2) qkv_gemm_kernel(
    const float* __restrict__ x, const float* __restrict__ Wq,
    const float* __restrict__ Wk, const float* __restrict__ Wv)
{
    __shared__ float As[2][128 * GAP];
    __shared__ float Bs[2][KC * GBP];

    const int sel = blockIdx.x;
    const float* W = (sel == 0) ? Wq : (sel == 1 ? Wk : Wv);
    float* outp = g_qkv[sel];
    const int m0 = blockIdx.y * 128;

    const int t = threadIdx.x;
    const int lane = t & 31, wid = t >> 5;
    const int wm = wid >> 1, wn = wid & 1;
    const int lq = lane >> 2, lr = lane & 3;

    const float* xp = x + (size_t)m0 * DM;

    float4 ra[2], rb[2];

    float c[2][8][4];
    #pragma unroll
    for (int mt = 0; mt < 2; mt++)
        #pragma unroll
        for (int nt = 0; nt < 8; nt++)
            #pragma unroll
            for (int k = 0; k < 4; k++) c[mt][nt][k] = 0.0f;

    #pragma unroll
    for (int i = 0; i < 2; i++) {
        int f = t + 256 * i;
        ra[i] = *(const float4*)(xp + (size_t)(f >> 2) * DM + (f & 3) * 4);
        rb[i] = *(const float4*)(W + (size_t)(f >> 5) * DK + (f & 31) * 4);
    }
    #pragma unroll
    for (int i = 0; i < 2; i++) {
        int f = t + 256 * i;
        float4 a = ra[i], bv = rb[i];
        float* ap = &As[0][(f >> 2) * GAP + (f & 3) * 4];
        ap[0] = f2tff(a.x); ap[1] = f2tff(a.y);
        ap[2] = f2tff(a.z); ap[3] = f2tff(a.w);
        float* bp = &Bs[0][(f >> 5) * GBP + (f & 31) * 4];
        bp[0] = f2tff(bv.x); bp[1] = f2tff(bv.y);
        bp[2] = f2tff(bv.z); bp[3] = f2tff(bv.w);
    }
    #pragma unroll
    for (int i = 0; i < 2; i++) {
        int f = t + 256 * i;
        ra[i] = *(const float4*)(xp + (size_t)(f >> 2) * DM + KC + (f & 3) * 4);
        rb[i] = *(const float4*)(W + (size_t)(KC + (f >> 5)) * DK + (f & 31) * 4);
    }
    __syncthreads();

    for (int kt = 0; kt < NIT; kt++) {
        const int p = kt & 1;

        #pragma unroll
        for (int kk = 0; kk < KC; kk += 8) {
            unsigned a[2][4];
            #pragma unroll
            for (int mt = 0; mt < 2; mt++) {
                int r = wm * 32 + mt * 16 + lq;
                a[mt][0] = __float_as_uint(As[p][r * GAP + kk + lr]);
                a[mt][1] = __float_as_uint(As[p][(r + 8) * GAP + kk + lr]);
                a[mt][2] = __float_as_uint(As[p][r * GAP + kk + 4 + lr]);
                a[mt][3] = __float_as_uint(As[p][(r + 8) * GAP + kk + 4 + lr]);
            }
            #pragma unroll
            for (int nt = 0; nt < 8; nt++) {
                int col = wn * 64 + nt * 8 + lq;
                unsigned b0 = __float_as_uint(Bs[p][(kk + lr) * GBP + col]);
                unsigned b1 = __float_as_uint(Bs[p][(kk + 4 + lr) * GBP + col]);
                MMA_TF32(c[0][nt], a[0][0], a[0][1], a[0][2], a[0][3], b0, b1);
                MMA_TF32(c[1][nt], a[1][0], a[1][1], a[1][2], a[1][3], b0, b1);
            }
        }

        if (kt + 1 < NIT) {
            #pragma unroll
            for (int i = 0; i < 2; i++) {
                int f = t + 256 * i;
                float4 a = ra[i], bv = rb[i];
                float* ap = &As[p ^ 1][(f >> 2) * GAP + (f & 3) * 4];
                ap[0] = f2tff(a.x); ap[1] = f2tff(a.y);
                ap[2] = f2tff(a.z); ap[3] = f2tff(a.w);
                float* bp = &Bs[p ^ 1][(f >> 5) * GBP + (f & 31) * 4];
                bp[0] = f2tff(bv.x); bp[1] = f2tff(bv.y);
                bp[2] = f2tff(bv.z); bp[3] = f2tff(bv.w);
            }
            if (kt + 2 < NIT) {
                const int k0 = (kt + 2) * KC;
                #pragma unroll
                for (int i = 0; i < 2; i++) {
                    int f = t + 256 * i;
                    ra[i] = *(const float4*)(xp + (size_t)(f >> 2) * DM + k0 + (f & 3) * 4);
                    rb[i] = *(const float4*)(W + (size_t)(k0 + (f >> 5)) * DK + (f & 31) * 4);
                }
            }
            __syncthreads();
        }
    }

    #pragma unroll
    for (int mt = 0; mt < 2; mt++) {
        int row = m0 + wm * 32 + mt * 16 + lq;
        #pragma unroll
        for (int nt = 0; nt < 8; nt++) {
            int col = wn * 64 + nt * 8 + 2 * lr;
            *(float2*)(outp + (size_t)row * DK + col) =
                make_float2(c[mt][nt][0], c[mt][nt][1]);
            *(float2*)(outp + (size_t)(row + 8) * DK + col) =
                make_float2(c[mt][nt][2], c[mt][nt][3]);
        }
    }
}

// ===========================================================================
// Flash attention (R11 body): BM=128 x BN=64, 8 full-row warps, register
// softmax, double-buffered K/V, 1 sync/iter, pi-permuted V (no PV shuffles).
// R17 schedule: grid (9, 16). CTA bx handles:
//   hh=0: q-tile 15-bx           (weights 16..7)
//   hh=1: q-tile bx-2 (if >= 0)  (weights 0-indexed: tiles 0..6)
// Groups: {15}=16u, {14}=15u, {13,0},{12,1},...,{7,6}=15u each. Max 16 units.
// ===========================================================================
struct __align__(16) AttnSmem {
    float Qf[128 * QFP];
    float Kf[2][128 * KFP];
    float Vf[2][128 * KFP];
};
extern __shared__ char attn_raw[];

__device__ __forceinline__ void sts_k(float* Kb, float4 v, int f) {
    int r = f >> 5, c4 = f & 31;
    int ng = r >> 3, lqq = r & 7, kkc = c4 >> 1, s = c4 & 1;
    float* kp = &Kb[(ng * 16 + kkc) * KFP + s];
    kp[(lqq * 4 + 0) * 2] = f2tff(v.x);
    kp[(lqq * 4 + 1) * 2] = f2tff(v.y);
    kp[(lqq * 4 + 2) * 2] = f2tff(v.z);
    kp[(lqq * 4 + 3) * 2] = f2tff(v.w);
}
// pi-permuted V store (pi(j)=2j / 2(j-4)+1): row g -> (lrr=g>>1, s=g&1)
__device__ __forceinline__ void sts_v(float* Vb, float4 v, int f) {
    int r = f >> 5, c4 = f & 31;
    int kkc = r >> 3, g = r & 7;
    int lrr = g >> 1, s = g & 1;
    int ng = c4 >> 1, lq0 = 4 * (c4 & 1);
    float* vp = &Vb[(kkc * 16 + ng) * KFP + lrr * 2 + s];
    vp[(lq0 + 0) * 8] = f2tff(v.x);
    vp[(lq0 + 1) * 8] = f2tff(v.y);
    vp[(lq0 + 2) * 8] = f2tff(v.z);
    vp[(lq0 + 3) * 8] = f2tff(v.w);
}

__global__ void __launch_bounds__(256, 1) attn_kernel(float* __restrict__ out)
{
    AttnSmem& sm = *reinterpret_cast<AttnSmem*>(attn_raw);
    const int t = threadIdx.x;
    const int lane = t & 31, wm = t >> 5;
    const int lq = lane >> 2, lr = lane & 3;
    const int b = blockIdx.y;

    const float* Q = g_qkv[0] + (size_t)b * T * DK;
    const float* K = g_qkv[1] + (size_t)b * T * DK;
    const float* V = g_qkv[2] + (size_t)b * T * DK;

    const float C = 0.12751744154255254f;   // (1/sqrt(128)) * log2(e)
    const int r1 = 16 * wm + lq;

    #pragma unroll 1
    for (int hh = 0; hh < 2; hh++) {
        const int qbi = hh ? ((int)blockIdx.x - 2) : (NQT - 1) - (int)blockIdx.x;
        if (qbi < 0) break;     // bx 0,1 have no second tile
        const int q0 = qbi * 128;

        if (hh) __syncthreads();   // half-0 tail done reading Qf / buffers

        // ---- Q -> fragment-major smem ----
        #pragma unroll
        for (int i = 0; i < 16; i++) {
            int f = t + 256 * i;
            int r = f >> 5, c4 = f & 31;
            float4 qv = *(const float4*)(Q + (size_t)(q0 + r) * DK + 4 * c4);
            int rg = r >> 4, lqq = r & 7, half = (r >> 3) & 1;
            int kkc = c4 >> 1, khalf = c4 & 1;
            float* qp = &sm.Qf[(rg * 16 + kkc) * QFP + half + 2 * khalf];
            qp[(lqq * 4 + 0) * 4] = f2tff(qv.x);
            qp[(lqq * 4 + 1) * 4] = f2tff(qv.y);
            qp[(lqq * 4 + 2) * 4] = f2tff(qv.z);
            qp[(lqq * 4 + 3) * 4] = f2tff(qv.w);
        }

        float4 kreg[8], vreg[8];
        #pragma unroll
        for (int i = 0; i < 8; i++) {
            int f = t + 256 * i;
            int r = f >> 5, c4 = f & 31;
            kreg[i] = *(const float4*)(K + (size_t)r * DK + 4 * c4);
            vreg[i] = *(const float4*)(V + (size_t)r * DK + 4 * c4);
        }
        #pragma unroll
        for (int i = 0; i < 8; i++) {
            sts_k(sm.Kf[0], kreg[i], t + 256 * i);
            sts_v(sm.Vf[0], vreg[i], t + 256 * i);
        }
        __syncthreads();

        float m1 = -1e30f, m2 = -1e30f, l1 = 0.0f, l2 = 0.0f;

        float o[16][4];
        #pragma unroll
        for (int ng = 0; ng < 16; ng++)
            #pragma unroll
            for (int k = 0; k < 4; k++) o[ng][k] = 0.0f;

        const float* qbase = &sm.Qf[(wm * 16) * QFP + lane * 4];
        const int qbend = 2 * qbi + 1;
        int p = 0;

        for (int kb = 0; kb <= qbend; kb++) {
            const int k0 = kb * 64;

            if (kb < qbend) {
                #pragma unroll
                for (int i = 0; i < 8; i++) {
                    int f = t + 256 * i;
                    kreg[i] = *(const float4*)(K + (size_t)(k0 + 64 + (f >> 5)) * DK + 4 * (f & 31));
                }
            }

            float sc[8][4];
            #pragma unroll
            for (int nt = 0; nt < 8; nt++)
                #pragma unroll
                for (int k = 0; k < 4; k++) sc[nt][k] = 0.0f;

            const float* kfb = &sm.Kf[p][lane * 2];
            #pragma unroll
            for (int kkc = 0; kkc < 16; kkc++) {
                float4 A = *(const float4*)(qbase + kkc * QFP);
                unsigned a0 = __float_as_uint(A.x), a1 = __float_as_uint(A.y);
                unsigned a2 = __float_as_uint(A.z), a3 = __float_as_uint(A.w);
                #pragma unroll
                for (int nt = 0; nt < 8; nt++) {
                    float2 Bv = *(const float2*)(kfb + (nt * 16 + kkc) * KFP);
                    MMA_TF32(sc[nt], a0, a1, a2, a3,
                             __float_as_uint(Bv.x), __float_as_uint(Bv.y));
                }
            }

            if (kb < qbend) {
                #pragma unroll
                for (int i = 0; i < 8; i++) {
                    int f = t + 256 * i;
                    vreg[i] = *(const float4*)(V + (size_t)(k0 + 64 + (f >> 5)) * DK + 4 * (f & 31));
                }
            }

            // causal mask on raw scores (scale folded into exp2 constant)
            if (kb >= 2 * qbi) {
                int gr1 = q0 + r1;
                #pragma unroll
                for (int nt = 0; nt < 8; nt++) {
                    int gc = k0 + nt * 8 + 2 * lr;
                    if (gc     > gr1)     sc[nt][0] = -1e30f;
                    if (gc + 1 > gr1)     sc[nt][1] = -1e30f;
                    if (gc     > gr1 + 8) sc[nt][2] = -1e30f;
                    if (gc + 1 > gr1 + 8) sc[nt][3] = -1e30f;
                }
            }

            float mx1 = -1e30f, mx2 = -1e30f;
            #pragma unroll
            for (int nt = 0; nt < 8; nt++) {
                mx1 = fmaxf(mx1, fmaxf(sc[nt][0], sc[nt][1]));
                mx2 = fmaxf(mx2, fmaxf(sc[nt][2], sc[nt][3]));
            }
            mx1 = fmaxf(mx1, __shfl_xor_sync(0xffffffffu, mx1, 1));
            mx1 = fmaxf(mx1, __shfl_xor_sync(0xffffffffu, mx1, 2));
            mx2 = fmaxf(mx2, __shfl_xor_sync(0xffffffffu, mx2, 1));
            mx2 = fmaxf(mx2, __shfl_xor_sync(0xffffffffu, mx2, 2));

            float mn1 = fmaxf(m1, mx1), mn2 = fmaxf(m2, mx2);
            float pc1 = fexp2((m1 - mn1) * C), pc2 = fexp2((m2 - mn2) * C);
            m1 = mn1; m2 = mn2;

            float s1 = 0.0f, s2 = 0.0f;
            #pragma unroll
            for (int nt = 0; nt < 8; nt++) {
                sc[nt][0] = fexp2((sc[nt][0] - m1) * C);
                sc[nt][1] = fexp2((sc[nt][1] - m1) * C);
                sc[nt][2] = fexp2((sc[nt][2] - m2) * C);
                sc[nt][3] = fexp2((sc[nt][3] - m2) * C);
                s1 += sc[nt][0] + sc[nt][1];
                s2 += sc[nt][2] + sc[nt][3];
            }
            s1 += __shfl_xor_sync(0xffffffffu, s1, 1);
            s1 += __shfl_xor_sync(0xffffffffu, s1, 2);
            s2 += __shfl_xor_sync(0xffffffffu, s2, 1);
            s2 += __shfl_xor_sync(0xffffffffu, s2, 2);
            l1 = l1 * pc1 + s1;
            l2 = l2 * pc2 + s2;

            #pragma unroll
            for (int ng = 0; ng < 16; ng++) {
                o[ng][0] *= pc1; o[ng][1] *= pc1;
                o[ng][2] *= pc2; o[ng][3] *= pc2;
            }

            // ---- PV: accumulators feed A fragments directly ----
            const float* vfb = &sm.Vf[p][lane * 2];
            #pragma unroll
            for (int c = 0; c < 8; c++) {
                unsigned a0 = f2tf(sc[c][0]);
                unsigned a1 = f2tf(sc[c][2]);
                unsigned a2 = f2tf(sc[c][1]);
                unsigned a3 = f2tf(sc[c][3]);
                const float* vb = vfb + (c * 16) * KFP;
                #pragma unroll
                for (int ng = 0; ng < 16; ng++) {
                    float2 Bv = *(const float2*)(vb + ng * KFP);
                    MMA_TF32(o[ng], a0, a1, a2, a3,
                             __float_as_uint(Bv.x), __float_as_uint(Bv.y));
                }
            }

            if (kb < qbend) {
                #pragma unroll
                for (int i = 0; i < 8; i++) {
                    sts_k(sm.Kf[p ^ 1], kreg[i], t + 256 * i);
                    sts_v(sm.Vf[p ^ 1], vreg[i], t + 256 * i);
                }
                __syncthreads();
            }
            p ^= 1;
        }

        // ---- epilogue: normalize and store this q-tile ----
        {
            float inv1 = 1.0f / l1, inv2 = 1.0f / l2;
            float* op = out + ((size_t)b * T + q0) * DK;
            #pragma unroll
            for (int ng = 0; ng < 16; ng++) {
                int cb = ng * 8 + 2 * lr;
                *(float2*)(op + (size_t)r1 * DK + cb) =
                    make_float2(o[ng][0] * inv1, o[ng][1] * inv1);
                *(float2*)(op + (size_t)(r1 + 8) * DK + cb) =
                    make_float2(o[ng][2] * inv2, o[ng][3] * inv2);
            }
        }
    }
}

// ===========================================================================
extern "C" void kernel_launch(void* const* d_in, const int* in_sizes, int n_in,
                              void* d_out, int out_size)
{
    const float* x  = (const float*)d_in[0];
    const float* Wq = (const float*)d_in[1];
    const float* Wk = (const float*)d_in[2];
    const float* Wv = (const float*)d_in[3];
    float* out = (float*)d_out;

    dim3 g1(3, BT / 128);
    qkv_gemm_kernel<<<g1, 256>>>(x, Wq, Wk, Wv);

    int asmem = (int)sizeof(AttnSmem);
    cudaFuncSetAttribute(attn_kernel, cudaFuncAttributeMaxDynamicSharedMemorySize, asmem);
    dim3 g2(9, NB);
    attn_kernel<<<g2, 256, (size_t)asmem>>>(out);
}